// round 10
// baseline (speedup 1.0000x reference)
#include <cuda_runtime.h>
#include <cuda_fp16.h>
#include <mma.h>
#include <math.h>
#include <stddef.h>
#include <stdint.h>

using namespace nvcuda;

#define B    16
#define CIN  512
#define COUT 512
#define HH   64
#define WW   64
#define SD   512
#define EPS  1e-8f

#define MOD_SCALE  0.04419417382415922f   // 1/sqrt(512)
#define CONV_SCALE 0.014731391274719738f  // 1/sqrt(512*9)

// padded, channel-last, scaled input: [B][66][66][512] fp16
#define XP 66
static __device__ __half g_xs[(size_t)B * XP * XP * CIN];
// weights channel-last per tap: [9][512 oc][512 ci] fp16
static __device__ __half g_wt[9 * COUT * CIN];
__device__ float g_s[B * CIN];
__device__ float g_demod[B * COUT];

__device__ __forceinline__ uint32_t smem_u32(const void* p) {
    uint32_t a;
    asm("{ .reg .u64 t; cvta.to.shared.u64 t, %1; cvt.u32.u64 %0, t; }"
        : "=r"(a) : "l"(p));
    return a;
}

#define MBAR_INIT(a, c) \
    asm volatile("mbarrier.init.shared.b64 [%0], %1;" :: "r"(a), "r"((uint32_t)(c)) : "memory")
#define MBAR_ARRIVE(a) \
    asm volatile("mbarrier.arrive.shared.b64 _, [%0];" :: "r"(a) : "memory")
#define MBAR_WAIT(a, ph) do {                                                        \
    asm volatile("{\n\t.reg .pred P1;\n\t"                                           \
        "WL%=:\n\tmbarrier.try_wait.parity.acquire.cta.shared::cta.b64 P1, [%0], %1, 0x989680;\n\t" \
        "@P1 bra.uni WD%=;\n\tbra.uni WL%=;\n\tWD%=:\n\t}"                           \
        :: "r"(a), "r"((uint32_t)(ph)) : "memory"); } while (0)
#define CPASYNC_MBAR_ARRIVE_NOINC(a) \
    asm volatile("cp.async.mbarrier.arrive.noinc.shared.b64 [%0];" :: "r"(a) : "memory")

// ---------------------------------------------------------------------------
// Kernel 1: s[b][i] = MOD_SCALE * (style[b,:] . mod_weight[i,:]) + mod_bias[i]
// ---------------------------------------------------------------------------
__global__ __launch_bounds__(256) void mod_kernel(
    const float* __restrict__ style, const float* __restrict__ mw,
    const float* __restrict__ mb)
{
    const int i = blockIdx.x, t = threadIdx.x;
    __shared__ float sh_style[B * SD];
    __shared__ float sh_w[SD];
    __shared__ float red[8][B];
    for (int idx = t; idx < B * SD; idx += 256) sh_style[idx] = style[idx];
    for (int d = t; d < SD; d += 256)           sh_w[d] = mw[(size_t)i * SD + d];
    __syncthreads();
    float acc[B];
#pragma unroll
    for (int b = 0; b < B; b++) acc[b] = 0.f;
    for (int d = t; d < SD; d += 256) {
        const float wv = sh_w[d];
#pragma unroll
        for (int b = 0; b < B; b++) acc[b] += wv * sh_style[b * SD + d];
    }
#pragma unroll
    for (int off = 16; off > 0; off >>= 1)
#pragma unroll
        for (int b = 0; b < B; b++)
            acc[b] += __shfl_down_sync(0xffffffffu, acc[b], off);
    const int warp = t >> 5, lane = t & 31;
    if (lane == 0)
#pragma unroll
        for (int b = 0; b < B; b++) red[warp][b] = acc[b];
    __syncthreads();
    if (t < B) {
        float v = 0.f;
#pragma unroll
        for (int w = 0; w < 8; w++) v += red[w][t];
        g_s[t * CIN + i] = v * MOD_SCALE + mb[i];
    }
}

// ---------------------------------------------------------------------------
// Kernel 2: demod[b][oc] = rsqrt(CONV_SCALE^2 * sum_i wsq[oc,i]*s[b,i]^2 + eps)
// ---------------------------------------------------------------------------
__global__ __launch_bounds__(256) void demod_kernel(const float* __restrict__ cw)
{
    const int oc = blockIdx.x, t = threadIdx.x;
    __shared__ float red[8][B];
    float acc[B];
#pragma unroll
    for (int b = 0; b < B; b++) acc[b] = 0.f;
    for (int i = t; i < CIN; i += 256) {
        const float* wp = cw + ((size_t)oc * CIN + i) * 9;
        float wsq = 0.f;
#pragma unroll
        for (int k = 0; k < 9; k++) { const float v = wp[k]; wsq += v * v; }
#pragma unroll
        for (int b = 0; b < B; b++) {
            const float s = g_s[b * CIN + i];
            acc[b] += wsq * s * s;
        }
    }
#pragma unroll
    for (int off = 16; off > 0; off >>= 1)
#pragma unroll
        for (int b = 0; b < B; b++)
            acc[b] += __shfl_down_sync(0xffffffffu, acc[b], off);
    const int warp = t >> 5, lane = t & 31;
    if (lane == 0)
#pragma unroll
        for (int b = 0; b < B; b++) red[warp][b] = acc[b];
    __syncthreads();
    if (t < B) {
        float v = 0.f;
#pragma unroll
        for (int w = 0; w < 8; w++) v += red[w][t];
        g_demod[t * COUT + oc] = rsqrtf(CONV_SCALE * CONV_SCALE * v + EPS);
    }
}

// ---------------------------------------------------------------------------
// Kernel 3: weight transpose: g_wt[tap][oc][ci] = fp16(W[oc][ci][tap])
// ---------------------------------------------------------------------------
__global__ __launch_bounds__(256) void wsplit_kernel(const float* __restrict__ cw)
{
    int idx = blockIdx.x * 256 + threadIdx.x;      // 9*512*512
    int ci  = idx & 511;
    int t1  = idx >> 9;
    int oc  = t1 & 511;
    int tap = t1 >> 9;
    float v = cw[((size_t)(oc << 9) + ci) * 9 + tap];
    g_wt[((size_t)tap << 18) + ((size_t)oc << 9) + ci] = __float2half(v);
}

// ---------------------------------------------------------------------------
// Kernel 4: zero padded borders of g_xs
// ---------------------------------------------------------------------------
__global__ void border_kernel()
{
    int i = blockIdx.x;           // 16*260
    int b = i / 260, r = i % 260;
    int h, w;
    if      (r <  66) { h = 0;           w = r;        }
    else if (r < 132) { h = 65;          w = r - 66;   }
    else if (r < 196) { h = r - 132 + 1; w = 0;        }
    else              { h = r - 196 + 1; w = 65;       }
    size_t base = (((size_t)b * XP + h) * XP + w) * CIN;
    int t = threadIdx.x;          // 128 threads x 8B = 1KB = 512 halves
    *(uint2*)((char*)g_xs + base * 2 + t * 8) = make_uint2(0, 0);
}

// ---------------------------------------------------------------------------
// Kernel 5: transpose + scale:  xs[b][h+1][w+1][ci] = fp16(CONV_SCALE*s*x)
// ---------------------------------------------------------------------------
__global__ __launch_bounds__(256) void xtrans_kernel(const float* __restrict__ x)
{
    const int cic = blockIdx.x, h = blockIdx.y, b = blockIdx.z;
    const int tid = threadIdx.x;
    const int ci0 = cic * 64;
    __shared__ float sT[64 * 65];
    __shared__ float sS[64];
    if (tid < 64) sS[tid] = CONV_SCALE * g_s[b * CIN + ci0 + tid];
#pragma unroll
    for (int it = 0; it < 16; it++) {
        int idx = it * 256 + tid;
        int cl = idx >> 6, w = idx & 63;
        sT[cl * 65 + w] = x[(((size_t)(b * CIN + ci0 + cl)) * HH + h) * WW + w];
    }
    __syncthreads();
#pragma unroll
    for (int it = 0; it < 16; it++) {
        int idx = it * 256 + tid;
        int w = idx >> 6, cl = idx & 63;
        float v = sS[cl] * sT[cl * 65 + w];
        size_t dst = (((size_t)b * XP + h + 1) * XP + (w + 1)) * CIN + ci0 + cl;
        g_xs[dst] = __float2half(v);
    }
}

// ---------------------------------------------------------------------------
// Kernel 6: main wmma (HMMA) implicit-GEMM conv, warp-specialized pipeline.
// CTA: 128 oc x 256 px (4h x 64w). 10 warps: 0-7 compute (warp tile 64x64),
// 8-9 producers (cp.async + mbarrier ring, 4 slots). No __syncthreads in loop.
// fp32 accum, demod in epilogue.   [R7 structure, ring depth 3 -> 4]
// ---------------------------------------------------------------------------
#define LDM 72                           // 64 halves data + 8 pad (144B rows)
#define A_BYTES (128 * LDM * 2)          // 18432
#define B_BYTES (256 * LDM * 2)          // 36864
#define STAGE_BYTES (A_BYTES + B_BYTES)  // 55296
#define NSTAGE 4
#define SMEM_DYN (NSTAGE * STAGE_BYTES)  // 221184
#define NTHREADS 320

__global__ __launch_bounds__(NTHREADS, 1) void conv_wmma_kernel(float* __restrict__ out)
{
    extern __shared__ char dynsmem[];
    __shared__ __align__(8) uint64_t sh_mbar[2 * NSTAGE];  // full[4], empty[4]

    const int tid = threadIdx.x;
    const int wid = tid >> 5;
    const int lane = tid & 31;

    const int bx = blockIdx.x;    // 16 b x 16 h-groups(4h)
    const int b  = bx >> 4;
    const int h0 = (bx & 15) * 4;
    const int oc0 = blockIdx.y * 128;

    const uint32_t s_u32 = smem_u32(dynsmem);
    const uint32_t mb_u32 = smem_u32(&sh_mbar[0]);
    // full[s] at mb_u32 + s*8, empty[s] at mb_u32 + NSTAGE*8 + s*8

    if (tid == 0) {
#pragma unroll
        for (int s = 0; s < NSTAGE; s++) {
            MBAR_INIT(mb_u32 + s * 8, 64);                // full: 64 producer threads
            MBAR_INIT(mb_u32 + NSTAGE * 8 + s * 8, 8);    // empty: 8 compute warps
        }
    }
    __syncthreads();

    if (wid >= 8) {
        // ---------------- producers (warps 8-9, 64 threads) ----------------
        const int ptid = tid - 256;              // 0..63
        int slot = 0, par = 1;                   // phase-flip trick: first NSTAGE waits pass
        for (int iter = 0; iter < 72; iter++) {
            MBAR_WAIT(mb_u32 + NSTAGE * 8 + slot * 8, par);

            const int tap = iter >> 3;
            const int ci0 = (iter & 7) * 64;
            const int kh = tap / 3, kw = tap - 3 * kh;
            const uint32_t st = s_u32 + slot * STAGE_BYTES;
            const __half* wbase = g_wt + ((size_t)tap << 18) + ci0;
            const __half* xbase = g_xs + ((((size_t)b * XP) + h0 + kh) * XP + kw) * CIN + ci0;
#pragma unroll
            for (int j = 0; j < 48; j++) {
                const int op = j * 64 + ptid;
                uint32_t dst;
                const __half* src;
                if (j < 16) {                    // A: ops 0..1023 (compile-time split)
                    const int r = op >> 3, c = op & 7;
                    dst = st + r * 144 + c * 16;
                    src = wbase + ((size_t)(oc0 + r) << 9) + c * 8;
                } else {                         // B: ops 1024..3071
                    const int idx = op - 1024;
                    const int r = idx >> 3, c = idx & 7;
                    dst = st + A_BYTES + r * 144 + c * 16;
                    src = xbase + ((size_t)((r >> 6) * XP + (r & 63)) << 9) + c * 8;
                }
                asm volatile("cp.async.ca.shared.global [%0], [%1], 16;"
                             :: "r"(dst), "l"(src));
            }
            CPASYNC_MBAR_ARRIVE_NOINC(mb_u32 + slot * 8);

            slot++; if (slot == NSTAGE) { slot = 0; par ^= 1; }
        }
    } else {
        // ---------------- consumers (warps 0-7) ----------------
        const int wm = wid & 1;       // warp M block (64 oc)
        const int wn = wid >> 1;      // warp N block (64 px)

        wmma::fragment<wmma::accumulator, 16, 16, 16, float> c[4][4];
#pragma unroll
        for (int mt = 0; mt < 4; mt++)
#pragma unroll
            for (int nt = 0; nt < 4; nt++) wmma::fill_fragment(c[mt][nt], 0.f);

        int slot = 0, par = 0;
        for (int iter = 0; iter < 72; iter++) {
            MBAR_WAIT(mb_u32 + slot * 8, par);

            const char* st = dynsmem + slot * STAGE_BYTES;
            const __half* sA = (const __half*)(st);
            const __half* sB = (const __half*)(st + A_BYTES);

#pragma unroll
            for (int ks = 0; ks < 4; ks++) {
                wmma::fragment<wmma::matrix_b, 16, 16, 16, __half, wmma::col_major> bf[4];
#pragma unroll
                for (int nt = 0; nt < 4; nt++)
                    wmma::load_matrix_sync(bf[nt], sB + (wn * 64 + nt * 16) * LDM + ks * 16, LDM);
#pragma unroll
                for (int mt = 0; mt < 4; mt++) {
                    wmma::fragment<wmma::matrix_a, 16, 16, 16, __half, wmma::row_major> af;
                    wmma::load_matrix_sync(af, sA + (wm * 64 + mt * 16) * LDM + ks * 16, LDM);
#pragma unroll
                    for (int nt = 0; nt < 4; nt++)
                        wmma::mma_sync(c[mt][nt], af, bf[nt], c[mt][nt]);
                }
            }
            if (lane == 0) MBAR_ARRIVE(mb_u32 + NSTAGE * 8 + slot * 8);

            slot++; if (slot == NSTAGE) { slot = 0; par ^= 1; }
        }

        __syncthreads();   // join producers before smem reuse

        // epilogue part 1: accum -> SMEM [128 oc][260 px]
        float* ep = (float*)dynsmem;
#pragma unroll
        for (int mt = 0; mt < 4; mt++)
#pragma unroll
            for (int nt = 0; nt < 4; nt++)
                wmma::store_matrix_sync(ep + (wm * 64 + mt * 16) * 260 + wn * 64 + nt * 16,
                                        c[mt][nt], 260, wmma::mem_row_major);
        goto epilogue_join;
    }
    __syncthreads();       // producers join here (matches consumers' first sync)
epilogue_join:
    __syncthreads();       // everyone: ep fully written

    // epilogue part 2: demod-scaled coalesced STG, all 320 threads
    {
        const float* ep = (const float*)dynsmem;
        for (int idx = tid; idx < 128 * 256; idx += NTHREADS) {
            const int oc = idx >> 8, p = idx & 255;
            const float dm = g_demod[b * COUT + oc0 + oc];
            out[(((size_t)b * COUT + oc0 + oc) * HH + h0 + (p >> 6)) * WW + (p & 63)] =
                ep[oc * 260 + p] * dm;
        }
    }
}

// ---------------------------------------------------------------------------
extern "C" void kernel_launch(void* const* d_in, const int* in_sizes, int n_in,
                              void* d_out, int out_size)
{
    const float* input       = (const float*)d_in[0];
    const float* style       = (const float*)d_in[1];
    const float* conv_weight = (const float*)d_in[2];
    const float* mod_weight  = (const float*)d_in[3];
    const float* mod_bias    = (const float*)d_in[4];
    float* out = (float*)d_out;

    mod_kernel<<<CIN, 256>>>(style, mod_weight, mod_bias);
    demod_kernel<<<COUT, 256>>>(conv_weight);
    wsplit_kernel<<<9 * COUT * CIN / 256, 256>>>(conv_weight);
    border_kernel<<<B * 260, 128>>>();
    xtrans_kernel<<<dim3(8, 64, 16), 256>>>(input);

    cudaFuncSetAttribute(conv_wmma_kernel,
                         cudaFuncAttributeMaxDynamicSharedMemorySize, SMEM_DYN);
    conv_wmma_kernel<<<dim3(256, 4), NTHREADS, SMEM_DYN>>>(out);
}

// round 11
// speedup vs baseline: 1.1750x; 1.1750x over previous
#include <cuda_runtime.h>
#include <cuda_fp16.h>
#include <mma.h>
#include <math.h>
#include <stddef.h>
#include <stdint.h>

using namespace nvcuda;

#define B    16
#define CIN  512
#define COUT 512
#define HH   64
#define WW   64
#define SD   512
#define EPS  1e-8f

#define MOD_SCALE  0.04419417382415922f   // 1/sqrt(512)
#define CONV_SCALE 0.014731391274719738f  // 1/sqrt(512*9)

// padded, channel-last, scaled input: [B][66][66][512] fp16
#define XP 66
static __device__ __half g_xs[(size_t)B * XP * XP * CIN];
// weights channel-last per tap: [9][512 oc][512 ci] fp16
static __device__ __half g_wt[9 * COUT * CIN];
__device__ float g_s[B * CIN];
__device__ float g_demod[B * COUT];

__device__ __forceinline__ uint32_t smem_u32(const void* p) {
    uint32_t a;
    asm("{ .reg .u64 t; cvta.to.shared.u64 t, %1; cvt.u32.u64 %0, t; }"
        : "=r"(a) : "l"(p));
    return a;
}

#define MBAR_INIT(a, c) \
    asm volatile("mbarrier.init.shared.b64 [%0], %1;" :: "r"(a), "r"((uint32_t)(c)) : "memory")
#define MBAR_ARRIVE(a) \
    asm volatile("mbarrier.arrive.shared.b64 _, [%0];" :: "r"(a) : "memory")
#define MBAR_WAIT(a, ph) do {                                                        \
    asm volatile("{\n\t.reg .pred P1;\n\t"                                           \
        "WL%=:\n\tmbarrier.try_wait.parity.acquire.cta.shared::cta.b64 P1, [%0], %1, 0x989680;\n\t" \
        "@P1 bra.uni WD%=;\n\tbra.uni WL%=;\n\tWD%=:\n\t}"                           \
        :: "r"(a), "r"((uint32_t)(ph)) : "memory"); } while (0)
#define CPASYNC_MBAR_ARRIVE_NOINC(a) \
    asm volatile("cp.async.mbarrier.arrive.noinc.shared.b64 [%0];" :: "r"(a) : "memory")

// ---------------------------------------------------------------------------
// Kernel 1: s[b][i] = MOD_SCALE * (style[b,:] . mod_weight[i,:]) + mod_bias[i]
// ---------------------------------------------------------------------------
__global__ __launch_bounds__(256) void mod_kernel(
    const float* __restrict__ style, const float* __restrict__ mw,
    const float* __restrict__ mb)
{
    const int i = blockIdx.x, t = threadIdx.x;
    __shared__ float sh_style[B * SD];
    __shared__ float sh_w[SD];
    __shared__ float red[8][B];
    for (int idx = t; idx < B * SD; idx += 256) sh_style[idx] = style[idx];
    for (int d = t; d < SD; d += 256)           sh_w[d] = mw[(size_t)i * SD + d];
    __syncthreads();
    float acc[B];
#pragma unroll
    for (int b = 0; b < B; b++) acc[b] = 0.f;
    for (int d = t; d < SD; d += 256) {
        const float wv = sh_w[d];
#pragma unroll
        for (int b = 0; b < B; b++) acc[b] += wv * sh_style[b * SD + d];
    }
#pragma unroll
    for (int off = 16; off > 0; off >>= 1)
#pragma unroll
        for (int b = 0; b < B; b++)
            acc[b] += __shfl_down_sync(0xffffffffu, acc[b], off);
    const int warp = t >> 5, lane = t & 31;
    if (lane == 0)
#pragma unroll
        for (int b = 0; b < B; b++) red[warp][b] = acc[b];
    __syncthreads();
    if (t < B) {
        float v = 0.f;
#pragma unroll
        for (int w = 0; w < 8; w++) v += red[w][t];
        g_s[t * CIN + i] = v * MOD_SCALE + mb[i];
    }
}

// ---------------------------------------------------------------------------
// Kernel 2: demod[b][oc] = rsqrt(CONV_SCALE^2 * sum_i wsq[oc,i]*s[b,i]^2 + eps)
// ---------------------------------------------------------------------------
__global__ __launch_bounds__(256) void demod_kernel(const float* __restrict__ cw)
{
    const int oc = blockIdx.x, t = threadIdx.x;
    __shared__ float red[8][B];
    float acc[B];
#pragma unroll
    for (int b = 0; b < B; b++) acc[b] = 0.f;
    for (int i = t; i < CIN; i += 256) {
        const float* wp = cw + ((size_t)oc * CIN + i) * 9;
        float wsq = 0.f;
#pragma unroll
        for (int k = 0; k < 9; k++) { const float v = wp[k]; wsq += v * v; }
#pragma unroll
        for (int b = 0; b < B; b++) {
            const float s = g_s[b * CIN + i];
            acc[b] += wsq * s * s;
        }
    }
#pragma unroll
    for (int off = 16; off > 0; off >>= 1)
#pragma unroll
        for (int b = 0; b < B; b++)
            acc[b] += __shfl_down_sync(0xffffffffu, acc[b], off);
    const int warp = t >> 5, lane = t & 31;
    if (lane == 0)
#pragma unroll
        for (int b = 0; b < B; b++) red[warp][b] = acc[b];
    __syncthreads();
    if (t < B) {
        float v = 0.f;
#pragma unroll
        for (int w = 0; w < 8; w++) v += red[w][t];
        g_demod[t * COUT + oc] = rsqrtf(CONV_SCALE * CONV_SCALE * v + EPS);
    }
}

// ---------------------------------------------------------------------------
// Kernel 3 (fused): weight transpose + zero padded borders of g_xs.
// Blocks [0, 9216):  g_wt[tap][oc][ci] = fp16(W[oc][ci][tap])
// Blocks [9216, 9216+4160): zero one 512-ch border row (256 thr x 4B = 1KB)
// ---------------------------------------------------------------------------
#define WSPLIT_BLOCKS (9 * COUT * CIN / 256)   // 9216
#define BORDER_BLOCKS (B * 260)                // 4160
__global__ __launch_bounds__(256) void prep_kernel(const float* __restrict__ cw)
{
    if (blockIdx.x < WSPLIT_BLOCKS) {
        int idx = blockIdx.x * 256 + threadIdx.x;      // 9*512*512
        int ci  = idx & 511;
        int t1  = idx >> 9;
        int oc  = t1 & 511;
        int tap = t1 >> 9;
        float v = cw[((size_t)(oc << 9) + ci) * 9 + tap];
        g_wt[((size_t)tap << 18) + ((size_t)oc << 9) + ci] = __float2half(v);
    } else {
        int i = blockIdx.x - WSPLIT_BLOCKS;   // 0..4159
        int b = i / 260, r = i % 260;
        int h, w;
        if      (r <  66) { h = 0;           w = r;        }
        else if (r < 132) { h = 65;          w = r - 66;   }
        else if (r < 196) { h = r - 132 + 1; w = 0;        }
        else              { h = r - 196 + 1; w = 65;       }
        size_t base = (((size_t)b * XP + h) * XP + w) * CIN;
        *(uint32_t*)((char*)g_xs + base * 2 + threadIdx.x * 4) = 0u;
    }
}

// ---------------------------------------------------------------------------
// Kernel 4: transpose + scale:  xs[b][h+1][w+1][ci] = fp16(CONV_SCALE*s*x)
// ---------------------------------------------------------------------------
__global__ __launch_bounds__(256) void xtrans_kernel(const float* __restrict__ x)
{
    const int cic = blockIdx.x, h = blockIdx.y, b = blockIdx.z;
    const int tid = threadIdx.x;
    const int ci0 = cic * 64;
    __shared__ float sT[64 * 65];
    __shared__ float sS[64];
    if (tid < 64) sS[tid] = CONV_SCALE * g_s[b * CIN + ci0 + tid];
#pragma unroll
    for (int it = 0; it < 16; it++) {
        int idx = it * 256 + tid;
        int cl = idx >> 6, w = idx & 63;
        sT[cl * 65 + w] = x[(((size_t)(b * CIN + ci0 + cl)) * HH + h) * WW + w];
    }
    __syncthreads();
#pragma unroll
    for (int it = 0; it < 16; it++) {
        int idx = it * 256 + tid;
        int w = idx >> 6, cl = idx & 63;
        float v = sS[cl] * sT[cl * 65 + w];
        size_t dst = (((size_t)b * XP + h + 1) * XP + (w + 1)) * CIN + ci0 + cl;
        g_xs[dst] = __float2half(v);
    }
}

// ---------------------------------------------------------------------------
// Kernel 5: main wmma (HMMA) implicit-GEMM conv, warp-specialized pipeline.
// CTA: 128 oc x 256 px (4h x 64w). 10 warps: 0-7 compute (warp tile 64x64),
// 8-9 producers (cp.async.cg + mbarrier ring, 3 slots). No __syncthreads in
// loop. fp32 accum, demod in epilogue.   [R7 structure; .ca -> .cg]
// ---------------------------------------------------------------------------
#define LDM 72                           // 64 halves data + 8 pad (144B rows)
#define A_BYTES (128 * LDM * 2)          // 18432
#define B_BYTES (256 * LDM * 2)          // 36864
#define STAGE_BYTES (A_BYTES + B_BYTES)  // 55296
#define NSTAGE 3
#define SMEM_DYN (NSTAGE * STAGE_BYTES)  // 165888
#define NTHREADS 320

__global__ __launch_bounds__(NTHREADS, 1) void conv_wmma_kernel(float* __restrict__ out)
{
    extern __shared__ char dynsmem[];
    __shared__ __align__(8) uint64_t sh_mbar[2 * NSTAGE];  // full[3], empty[3]

    const int tid = threadIdx.x;
    const int wid = tid >> 5;
    const int lane = tid & 31;

    const int bx = blockIdx.x;    // 16 b x 16 h-groups(4h)
    const int b  = bx >> 4;
    const int h0 = (bx & 15) * 4;
    const int oc0 = blockIdx.y * 128;

    const uint32_t s_u32 = smem_u32(dynsmem);
    const uint32_t mb_u32 = smem_u32(&sh_mbar[0]);
    // full[s] at mb_u32 + s*8, empty[s] at mb_u32 + NSTAGE*8 + s*8

    if (tid == 0) {
#pragma unroll
        for (int s = 0; s < NSTAGE; s++) {
            MBAR_INIT(mb_u32 + s * 8, 64);                // full: 64 producer threads
            MBAR_INIT(mb_u32 + NSTAGE * 8 + s * 8, 8);    // empty: 8 compute warps
        }
    }
    __syncthreads();

    if (wid >= 8) {
        // ---------------- producers (warps 8-9, 64 threads) ----------------
        const int ptid = tid - 256;              // 0..63
        int slot = 0, par = 1;                   // phase-flip trick: first NSTAGE waits pass
        for (int iter = 0; iter < 72; iter++) {
            MBAR_WAIT(mb_u32 + NSTAGE * 8 + slot * 8, par);

            const int tap = iter >> 3;
            const int ci0 = (iter & 7) * 64;
            const int kh = tap / 3, kw = tap - 3 * kh;
            const uint32_t st = s_u32 + slot * STAGE_BYTES;
            const __half* wbase = g_wt + ((size_t)tap << 18) + ci0;
            const __half* xbase = g_xs + ((((size_t)b * XP) + h0 + kh) * XP + kw) * CIN + ci0;
#pragma unroll
            for (int j = 0; j < 48; j++) {
                const int op = j * 64 + ptid;
                uint32_t dst;
                const __half* src;
                if (j < 16) {                    // A: ops 0..1023 (compile-time split)
                    const int r = op >> 3, c = op & 7;
                    dst = st + r * 144 + c * 16;
                    src = wbase + ((size_t)(oc0 + r) << 9) + c * 8;
                } else {                         // B: ops 1024..3071
                    const int idx = op - 1024;
                    const int r = idx >> 3, c = idx & 7;
                    dst = st + A_BYTES + r * 144 + c * 16;
                    src = xbase + ((size_t)((r >> 6) * XP + (r & 63)) << 9) + c * 8;
                }
                asm volatile("cp.async.cg.shared.global [%0], [%1], 16;"
                             :: "r"(dst), "l"(src));
            }
            CPASYNC_MBAR_ARRIVE_NOINC(mb_u32 + slot * 8);

            slot++; if (slot == NSTAGE) { slot = 0; par ^= 1; }
        }
    } else {
        // ---------------- consumers (warps 0-7) ----------------
        const int wm = wid & 1;       // warp M block (64 oc)
        const int wn = wid >> 1;      // warp N block (64 px)

        wmma::fragment<wmma::accumulator, 16, 16, 16, float> c[4][4];
#pragma unroll
        for (int mt = 0; mt < 4; mt++)
#pragma unroll
            for (int nt = 0; nt < 4; nt++) wmma::fill_fragment(c[mt][nt], 0.f);

        int slot = 0, par = 0;
        for (int iter = 0; iter < 72; iter++) {
            MBAR_WAIT(mb_u32 + slot * 8, par);

            const char* st = dynsmem + slot * STAGE_BYTES;
            const __half* sA = (const __half*)(st);
            const __half* sB = (const __half*)(st + A_BYTES);

#pragma unroll
            for (int ks = 0; ks < 4; ks++) {
                wmma::fragment<wmma::matrix_b, 16, 16, 16, __half, wmma::col_major> bf[4];
#pragma unroll
                for (int nt = 0; nt < 4; nt++)
                    wmma::load_matrix_sync(bf[nt], sB + (wn * 64 + nt * 16) * LDM + ks * 16, LDM);
#pragma unroll
                for (int mt = 0; mt < 4; mt++) {
                    wmma::fragment<wmma::matrix_a, 16, 16, 16, __half, wmma::row_major> af;
                    wmma::load_matrix_sync(af, sA + (wm * 64 + mt * 16) * LDM + ks * 16, LDM);
#pragma unroll
                    for (int nt = 0; nt < 4; nt++)
                        wmma::mma_sync(c[mt][nt], af, bf[nt], c[mt][nt]);
                }
            }
            if (lane == 0) MBAR_ARRIVE(mb_u32 + NSTAGE * 8 + slot * 8);

            slot++; if (slot == NSTAGE) { slot = 0; par ^= 1; }
        }

        __syncthreads();   // join producers before smem reuse

        // epilogue part 1: accum -> SMEM [128 oc][260 px]
        float* ep = (float*)dynsmem;
#pragma unroll
        for (int mt = 0; mt < 4; mt++)
#pragma unroll
            for (int nt = 0; nt < 4; nt++)
                wmma::store_matrix_sync(ep + (wm * 64 + mt * 16) * 260 + wn * 64 + nt * 16,
                                        c[mt][nt], 260, wmma::mem_row_major);
        goto epilogue_join;
    }
    __syncthreads();       // producers join here (matches consumers' first sync)
epilogue_join:
    __syncthreads();       // everyone: ep fully written

    // epilogue part 2: demod-scaled coalesced STG, all 320 threads
    {
        const float* ep = (const float*)dynsmem;
        for (int idx = tid; idx < 128 * 256; idx += NTHREADS) {
            const int oc = idx >> 8, p = idx & 255;
            const float dm = g_demod[b * COUT + oc0 + oc];
            out[(((size_t)b * COUT + oc0 + oc) * HH + h0 + (p >> 6)) * WW + (p & 63)] =
                ep[oc * 260 + p] * dm;
        }
    }
}

// ---------------------------------------------------------------------------
extern "C" void kernel_launch(void* const* d_in, const int* in_sizes, int n_in,
                              void* d_out, int out_size)
{
    const float* input       = (const float*)d_in[0];
    const float* style       = (const float*)d_in[1];
    const float* conv_weight = (const float*)d_in[2];
    const float* mod_weight  = (const float*)d_in[3];
    const float* mod_bias    = (const float*)d_in[4];
    float* out = (float*)d_out;

    mod_kernel<<<CIN, 256>>>(style, mod_weight, mod_bias);
    demod_kernel<<<COUT, 256>>>(conv_weight);
    prep_kernel<<<WSPLIT_BLOCKS + BORDER_BLOCKS, 256>>>(conv_weight);
    xtrans_kernel<<<dim3(8, 64, 16), 256>>>(input);

    cudaFuncSetAttribute(conv_wmma_kernel,
                         cudaFuncAttributeMaxDynamicSharedMemorySize, SMEM_DYN);
    conv_wmma_kernel<<<dim3(256, 4), NTHREADS, SMEM_DYN>>>(out);
}

// round 12
// speedup vs baseline: 1.2043x; 1.0250x over previous
#include <cuda_runtime.h>
#include <cuda_fp16.h>
#include <mma.h>
#include <math.h>
#include <stddef.h>
#include <stdint.h>

using namespace nvcuda;

#define B    16
#define CIN  512
#define COUT 512
#define HH   64
#define WW   64
#define SD   512
#define EPS  1e-8f

#define MOD_SCALE  0.04419417382415922f   // 1/sqrt(512)
#define CONV_SCALE 0.014731391274719738f  // 1/sqrt(512*9)

// padded, channel-last, scaled input: [B][66][66][512] fp16
#define XP 66
static __device__ __half g_xs[(size_t)B * XP * XP * CIN];
// weights channel-last per tap: [9][512 oc][512 ci] fp16
static __device__ __half g_wt[9 * COUT * CIN];
__device__ float g_s[B * CIN];
__device__ float g_demod[B * COUT];

__device__ __forceinline__ uint32_t smem_u32(const void* p) {
    uint32_t a;
    asm("{ .reg .u64 t; cvta.to.shared.u64 t, %1; cvt.u32.u64 %0, t; }"
        : "=r"(a) : "l"(p));
    return a;
}

#define MBAR_INIT(a, c) \
    asm volatile("mbarrier.init.shared.b64 [%0], %1;" :: "r"(a), "r"((uint32_t)(c)) : "memory")
#define MBAR_ARRIVE(a) \
    asm volatile("mbarrier.arrive.shared.b64 _, [%0];" :: "r"(a) : "memory")
#define MBAR_WAIT(a, ph) do {                                                        \
    asm volatile("{\n\t.reg .pred P1;\n\t"                                           \
        "WL%=:\n\tmbarrier.try_wait.parity.acquire.cta.shared::cta.b64 P1, [%0], %1, 0x989680;\n\t" \
        "@P1 bra.uni WD%=;\n\tbra.uni WL%=;\n\tWD%=:\n\t}"                           \
        :: "r"(a), "r"((uint32_t)(ph)) : "memory"); } while (0)
#define CPASYNC_MBAR_ARRIVE_NOINC(a) \
    asm volatile("cp.async.mbarrier.arrive.noinc.shared.b64 [%0];" :: "r"(a) : "memory")

// ---------------------------------------------------------------------------
// Kernel 1: s[b][i] = MOD_SCALE * (style[b,:] . mod_weight[i,:]) + mod_bias[i]
// ---------------------------------------------------------------------------
__global__ __launch_bounds__(256) void mod_kernel(
    const float* __restrict__ style, const float* __restrict__ mw,
    const float* __restrict__ mb)
{
    const int i = blockIdx.x, t = threadIdx.x;
    __shared__ float sh_style[B * SD];
    __shared__ float sh_w[SD];
    __shared__ float red[8][B];
    for (int idx = t; idx < B * SD; idx += 256) sh_style[idx] = style[idx];
    for (int d = t; d < SD; d += 256)           sh_w[d] = mw[(size_t)i * SD + d];
    __syncthreads();
    float acc[B];
#pragma unroll
    for (int b = 0; b < B; b++) acc[b] = 0.f;
    for (int d = t; d < SD; d += 256) {
        const float wv = sh_w[d];
#pragma unroll
        for (int b = 0; b < B; b++) acc[b] += wv * sh_style[b * SD + d];
    }
#pragma unroll
    for (int off = 16; off > 0; off >>= 1)
#pragma unroll
        for (int b = 0; b < B; b++)
            acc[b] += __shfl_down_sync(0xffffffffu, acc[b], off);
    const int warp = t >> 5, lane = t & 31;
    if (lane == 0)
#pragma unroll
        for (int b = 0; b < B; b++) red[warp][b] = acc[b];
    __syncthreads();
    if (t < B) {
        float v = 0.f;
#pragma unroll
        for (int w = 0; w < 8; w++) v += red[w][t];
        g_s[t * CIN + i] = v * MOD_SCALE + mb[i];
    }
}

// ---------------------------------------------------------------------------
// Kernel 2: demod[b][oc] = rsqrt(CONV_SCALE^2 * sum_i wsq[oc,i]*s[b,i]^2 + eps)
// ---------------------------------------------------------------------------
__global__ __launch_bounds__(256) void demod_kernel(const float* __restrict__ cw)
{
    const int oc = blockIdx.x, t = threadIdx.x;
    __shared__ float red[8][B];
    float acc[B];
#pragma unroll
    for (int b = 0; b < B; b++) acc[b] = 0.f;
    for (int i = t; i < CIN; i += 256) {
        const float* wp = cw + ((size_t)oc * CIN + i) * 9;
        float wsq = 0.f;
#pragma unroll
        for (int k = 0; k < 9; k++) { const float v = wp[k]; wsq += v * v; }
#pragma unroll
        for (int b = 0; b < B; b++) {
            const float s = g_s[b * CIN + i];
            acc[b] += wsq * s * s;
        }
    }
#pragma unroll
    for (int off = 16; off > 0; off >>= 1)
#pragma unroll
        for (int b = 0; b < B; b++)
            acc[b] += __shfl_down_sync(0xffffffffu, acc[b], off);
    const int warp = t >> 5, lane = t & 31;
    if (lane == 0)
#pragma unroll
        for (int b = 0; b < B; b++) red[warp][b] = acc[b];
    __syncthreads();
    if (t < B) {
        float v = 0.f;
#pragma unroll
        for (int w = 0; w < 8; w++) v += red[w][t];
        g_demod[t * COUT + oc] = rsqrtf(CONV_SCALE * CONV_SCALE * v + EPS);
    }
}

// ---------------------------------------------------------------------------
// Kernel 3 (fused): weight transpose + zero padded borders of g_xs.
// ---------------------------------------------------------------------------
#define WSPLIT_BLOCKS (9 * COUT * CIN / 256)   // 9216
#define BORDER_BLOCKS (B * 260)                // 4160
__global__ __launch_bounds__(256) void prep_kernel(const float* __restrict__ cw)
{
    if (blockIdx.x < WSPLIT_BLOCKS) {
        int idx = blockIdx.x * 256 + threadIdx.x;      // 9*512*512
        int ci  = idx & 511;
        int t1  = idx >> 9;
        int oc  = t1 & 511;
        int tap = t1 >> 9;
        float v = cw[((size_t)(oc << 9) + ci) * 9 + tap];
        g_wt[((size_t)tap << 18) + ((size_t)oc << 9) + ci] = __float2half(v);
    } else {
        int i = blockIdx.x - WSPLIT_BLOCKS;   // 0..4159
        int b = i / 260, r = i % 260;
        int h, w;
        if      (r <  66) { h = 0;           w = r;        }
        else if (r < 132) { h = 65;          w = r - 66;   }
        else if (r < 196) { h = r - 132 + 1; w = 0;        }
        else              { h = r - 196 + 1; w = 65;       }
        size_t base = (((size_t)b * XP + h) * XP + w) * CIN;
        *(uint32_t*)((char*)g_xs + base * 2 + threadIdx.x * 4) = 0u;
    }
}

// ---------------------------------------------------------------------------
// Kernel 4: transpose + scale:  xs[b][h+1][w+1][ci] = fp16(CONV_SCALE*s*x)
// float4 reads, __half2 stores (full-width warp transactions).
// ---------------------------------------------------------------------------
__global__ __launch_bounds__(256) void xtrans_kernel(const float* __restrict__ x)
{
    const int cic = blockIdx.x, h = blockIdx.y, b = blockIdx.z;
    const int tid = threadIdx.x;
    const int ci0 = cic * 64;
    __shared__ float sT[64 * 65];
    __shared__ float sS[64];
    if (tid < 64) sS[tid] = CONV_SCALE * g_s[b * CIN + ci0 + tid];
#pragma unroll
    for (int it = 0; it < 4; it++) {           // 1024 float4 ops = 64 rows x 16
        int idx = it * 256 + tid;
        int cl = idx >> 4, wq = idx & 15;
        float4 v = *(const float4*)&x[(((size_t)(b * CIN + ci0 + cl)) * HH + h) * WW + wq * 4];
        float* d = &sT[cl * 65 + wq * 4];
        d[0] = v.x; d[1] = v.y; d[2] = v.z; d[3] = v.w;
    }
    __syncthreads();
#pragma unroll
    for (int it = 0; it < 8; it++) {           // 2048 half2 ops = 64 w x 32 pairs
        int idx = it * 256 + tid;
        int w = idx >> 5, clp = idx & 31;
        int cl = clp * 2;
        float v0 = sS[cl]     * sT[cl * 65 + w];
        float v1 = sS[cl + 1] * sT[(cl + 1) * 65 + w];
        size_t dst = (((size_t)b * XP + h + 1) * XP + (w + 1)) * CIN + ci0 + cl;
        *(__half2*)&g_xs[dst] = __floats2half2_rn(v0, v1);
    }
}

// ---------------------------------------------------------------------------
// Kernel 5: main wmma (HMMA) implicit-GEMM conv, warp-specialized pipeline.
// CTA: 128 oc x 256 px (4h x 64w). 10 warps: 0-7 compute (warp tile 64x64),
// 8-9 producers (cp.async.ca + mbarrier ring, 3 slots). No __syncthreads in
// loop. fp32 accum, demod in epilogue.   [R7 exact configuration]
// ---------------------------------------------------------------------------
#define LDM 72                           // 64 halves data + 8 pad (144B rows)
#define A_BYTES (128 * LDM * 2)          // 18432
#define B_BYTES (256 * LDM * 2)          // 36864
#define STAGE_BYTES (A_BYTES + B_BYTES)  // 55296
#define NSTAGE 3
#define SMEM_DYN (NSTAGE * STAGE_BYTES)  // 165888
#define NTHREADS 320

__global__ __launch_bounds__(NTHREADS, 1) void conv_wmma_kernel(float* __restrict__ out)
{
    extern __shared__ char dynsmem[];
    __shared__ __align__(8) uint64_t sh_mbar[2 * NSTAGE];  // full[3], empty[3]

    const int tid = threadIdx.x;
    const int wid = tid >> 5;
    const int lane = tid & 31;

    const int bx = blockIdx.x;    // 16 b x 16 h-groups(4h)
    const int b  = bx >> 4;
    const int h0 = (bx & 15) * 4;
    const int oc0 = blockIdx.y * 128;

    const uint32_t s_u32 = smem_u32(dynsmem);
    const uint32_t mb_u32 = smem_u32(&sh_mbar[0]);
    // full[s] at mb_u32 + s*8, empty[s] at mb_u32 + NSTAGE*8 + s*8

    if (tid == 0) {
#pragma unroll
        for (int s = 0; s < NSTAGE; s++) {
            MBAR_INIT(mb_u32 + s * 8, 64);                // full: 64 producer threads
            MBAR_INIT(mb_u32 + NSTAGE * 8 + s * 8, 8);    // empty: 8 compute warps
        }
    }
    __syncthreads();

    if (wid >= 8) {
        // ---------------- producers (warps 8-9, 64 threads) ----------------
        const int ptid = tid - 256;              // 0..63
        int slot = 0, par = 1;                   // phase-flip trick: first NSTAGE waits pass
        for (int iter = 0; iter < 72; iter++) {
            MBAR_WAIT(mb_u32 + NSTAGE * 8 + slot * 8, par);

            const int tap = iter >> 3;
            const int ci0 = (iter & 7) * 64;
            const int kh = tap / 3, kw = tap - 3 * kh;
            const uint32_t st = s_u32 + slot * STAGE_BYTES;
            const __half* wbase = g_wt + ((size_t)tap << 18) + ci0;
            const __half* xbase = g_xs + ((((size_t)b * XP) + h0 + kh) * XP + kw) * CIN + ci0;
#pragma unroll
            for (int j = 0; j < 48; j++) {
                const int op = j * 64 + ptid;
                uint32_t dst;
                const __half* src;
                if (j < 16) {                    // A: ops 0..1023 (compile-time split)
                    const int r = op >> 3, c = op & 7;
                    dst = st + r * 144 + c * 16;
                    src = wbase + ((size_t)(oc0 + r) << 9) + c * 8;
                } else {                         // B: ops 1024..3071
                    const int idx = op - 1024;
                    const int r = idx >> 3, c = idx & 7;
                    dst = st + A_BYTES + r * 144 + c * 16;
                    src = xbase + ((size_t)((r >> 6) * XP + (r & 63)) << 9) + c * 8;
                }
                asm volatile("cp.async.ca.shared.global [%0], [%1], 16;"
                             :: "r"(dst), "l"(src));
            }
            CPASYNC_MBAR_ARRIVE_NOINC(mb_u32 + slot * 8);

            slot++; if (slot == NSTAGE) { slot = 0; par ^= 1; }
        }
    } else {
        // ---------------- consumers (warps 0-7) ----------------
        const int wm = wid & 1;       // warp M block (64 oc)
        const int wn = wid >> 1;      // warp N block (64 px)

        wmma::fragment<wmma::accumulator, 16, 16, 16, float> c[4][4];
#pragma unroll
        for (int mt = 0; mt < 4; mt++)
#pragma unroll
            for (int nt = 0; nt < 4; nt++) wmma::fill_fragment(c[mt][nt], 0.f);

        int slot = 0, par = 0;
        for (int iter = 0; iter < 72; iter++) {
            MBAR_WAIT(mb_u32 + slot * 8, par);

            const char* st = dynsmem + slot * STAGE_BYTES;
            const __half* sA = (const __half*)(st);
            const __half* sB = (const __half*)(st + A_BYTES);

#pragma unroll
            for (int ks = 0; ks < 4; ks++) {
                wmma::fragment<wmma::matrix_b, 16, 16, 16, __half, wmma::col_major> bf[4];
#pragma unroll
                for (int nt = 0; nt < 4; nt++)
                    wmma::load_matrix_sync(bf[nt], sB + (wn * 64 + nt * 16) * LDM + ks * 16, LDM);
#pragma unroll
                for (int mt = 0; mt < 4; mt++) {
                    wmma::fragment<wmma::matrix_a, 16, 16, 16, __half, wmma::row_major> af;
                    wmma::load_matrix_sync(af, sA + (wm * 64 + mt * 16) * LDM + ks * 16, LDM);
#pragma unroll
                    for (int nt = 0; nt < 4; nt++)
                        wmma::mma_sync(c[mt][nt], af, bf[nt], c[mt][nt]);
                }
            }
            if (lane == 0) MBAR_ARRIVE(mb_u32 + NSTAGE * 8 + slot * 8);

            slot++; if (slot == NSTAGE) { slot = 0; par ^= 1; }
        }

        __syncthreads();   // join producers before smem reuse

        // epilogue part 1: accum -> SMEM [128 oc][260 px]
        float* ep = (float*)dynsmem;
#pragma unroll
        for (int mt = 0; mt < 4; mt++)
#pragma unroll
            for (int nt = 0; nt < 4; nt++)
                wmma::store_matrix_sync(ep + (wm * 64 + mt * 16) * 260 + wn * 64 + nt * 16,
                                        c[mt][nt], 260, wmma::mem_row_major);
        goto epilogue_join;
    }
    __syncthreads();       // producers join here (matches consumers' first sync)
epilogue_join:
    __syncthreads();       // everyone: ep fully written

    // epilogue part 2: demod-scaled coalesced STG, all 320 threads
    {
        const float* ep = (const float*)dynsmem;
        for (int idx = tid; idx < 128 * 256; idx += NTHREADS) {
            const int oc = idx >> 8, p = idx & 255;
            const float dm = g_demod[b * COUT + oc0 + oc];
            out[(((size_t)b * COUT + oc0 + oc) * HH + h0 + (p >> 6)) * WW + (p & 63)] =
                ep[oc * 260 + p] * dm;
        }
    }
}

// ---------------------------------------------------------------------------
extern "C" void kernel_launch(void* const* d_in, const int* in_sizes, int n_in,
                              void* d_out, int out_size)
{
    const float* input       = (const float*)d_in[0];
    const float* style       = (const float*)d_in[1];
    const float* conv_weight = (const float*)d_in[2];
    const float* mod_weight  = (const float*)d_in[3];
    const float* mod_bias    = (const float*)d_in[4];
    float* out = (float*)d_out;

    mod_kernel<<<CIN, 256>>>(style, mod_weight, mod_bias);
    demod_kernel<<<COUT, 256>>>(conv_weight);
    prep_kernel<<<WSPLIT_BLOCKS + BORDER_BLOCKS, 256>>>(conv_weight);
    xtrans_kernel<<<dim3(8, 64, 16), 256>>>(input);

    cudaFuncSetAttribute(conv_wmma_kernel,
                         cudaFuncAttributeMaxDynamicSharedMemorySize, SMEM_DYN);
    conv_wmma_kernel<<<dim3(256, 4), NTHREADS, SMEM_DYN>>>(out);
}